// round 3
// baseline (speedup 1.0000x reference)
#include <cuda_runtime.h>
#include <cuda_bf16.h>
#include <math.h>

#define HID   64
#define TT    128
#define FF    32
#define NA    100
#define NQ    8             // groups of 64 threads
#define NBQ   8             // batch elems per thread
#define BB    (NQ*NBQ)      // 64 batch elems per block
#define NTHREADS (NQ*64)    // 512
#define HS    68            // h/xs row stride in floats (68%32==4 -> conflict-free .128)
#define WLS   102           // wlin shared stride

struct Smem {
    float4 wih[FF*64];      // [f][j] gate-packed (i,f,g,o)   32 KB
    float4 whh[HID*64];     // [k][j] gate-packed             64 KB
    float4 b4g[64];         // combined bias per j             1 KB
    float  h[HID][HS];      // [j'][batch]                    17 KB
    float  xs[FF][HS];      // [f][batch]                      8.5 KB
    float  wlin[HID*WLS];   // [j'][asset]                    25.5 KB
};

// ---- f32x2 packed helpers (sm_100a, PTX ISA 8.6) ----
typedef unsigned long long u64;

__device__ __forceinline__ u64 dup2(float v) {
    u64 r; asm("mov.b64 %0, {%1, %1};" : "=l"(r) : "f"(v)); return r;
}
__device__ __forceinline__ u64 pack2(float lo, float hi) {
    u64 r; asm("mov.b64 %0, {%1, %2};" : "=l"(r) : "f"(lo), "f"(hi)); return r;
}
__device__ __forceinline__ void ffma2(u64& d, u64 a, u64 b) {
    asm("fma.rn.f32x2 %0, %1, %2, %0;" : "+l"(d) : "l"(a), "l"(b));
}
__device__ __forceinline__ float2 unpack2(u64 v) {
    float2 r; asm("mov.b64 {%0, %1}, %2;" : "=f"(r.x), "=f"(r.y) : "l"(v)); return r;
}

__device__ __forceinline__ float sigm(float v) {
    return __fdividef(1.f, 1.f + __expf(-v));
}
__device__ __forceinline__ float tanh_fast(float v) {
    float a = fabsf(v);
    float e = __expf(-2.f * a);
    float t = __fdividef(1.f - e, 1.f + e);
    return copysignf(t, v);
}

__global__ __launch_bounds__(NTHREADS, 1)
void lstm_fused_kernel(const float* __restrict__ x,
                       const float* __restrict__ Wih,
                       const float* __restrict__ Whh,
                       const float* __restrict__ bih,
                       const float* __restrict__ bhh,
                       const float* __restrict__ Wlin,
                       const float* __restrict__ blin,
                       float* __restrict__ out)
{
    extern __shared__ char smem_raw[];
    Smem* s = reinterpret_cast<Smem*>(smem_raw);

    const int tid   = threadIdx.x;
    const int j     = tid & 63;
    const int q     = tid >> 6;
    const int bbase = q * NBQ;
    const int gb0   = blockIdx.x * BB;

    // ---- preload weights (gate-packed, transposed) ----
    for (int idx = tid; idx < FF*64; idx += NTHREADS) {
        int f = idx >> 6, jj = idx & 63;
        s->wih[idx] = make_float4(Wih[(0*HID + jj)*FF + f],
                                  Wih[(1*HID + jj)*FF + f],
                                  Wih[(2*HID + jj)*FF + f],
                                  Wih[(3*HID + jj)*FF + f]);
    }
    for (int idx = tid; idx < HID*64; idx += NTHREADS) {
        int k = idx >> 6, jj = idx & 63;
        s->whh[idx] = make_float4(Whh[(0*HID + jj)*HID + k],
                                  Whh[(1*HID + jj)*HID + k],
                                  Whh[(2*HID + jj)*HID + k],
                                  Whh[(3*HID + jj)*HID + k]);
    }
    for (int idx = tid; idx < 64; idx += NTHREADS) {
        s->b4g[idx] = make_float4(bih[0*HID+idx] + bhh[0*HID+idx],
                                  bih[1*HID+idx] + bhh[1*HID+idx],
                                  bih[2*HID+idx] + bhh[2*HID+idx],
                                  bih[3*HID+idx] + bhh[3*HID+idx]);
    }
    for (int idx = tid; idx < HID*HS; idx += NTHREADS)
        (&s->h[0][0])[idx] = 0.f;

    float c[NBQ];
    u64 pl0[4], pl1[4];   // batch-pair-packed logits for assets a0, a0+1
    #pragma unroll
    for (int b = 0; b < NBQ; b++) c[b] = 0.f;
    #pragma unroll
    for (int p = 0; p < 4; p++) { pl0[p] = 0ull; pl1[p] = 0ull; }

    const int  a0    = 2 * j;
    const bool has_a = (a0 < NA);

    __syncthreads();

    // duplicated biases (per gate), constant over t
    u64 bias2[4];
    {
        float4 bb = s->b4g[j];
        bias2[0] = dup2(bb.x); bias2[1] = dup2(bb.y);
        bias2[2] = dup2(bb.z); bias2[3] = dup2(bb.w);
    }

    for (int t = 0; t < TT; t++) {
        // ---- stage x_t transposed: xs[f][b], BB*FF = 2048 floats ----
        #pragma unroll
        for (int r = 0; r < (BB*FF)/NTHREADS; r++) {
            int ii = tid + r*NTHREADS;
            int b = ii >> 5, f = ii & 31;
            s->xs[f][b] = x[(size_t)(gb0 + b)*(TT*FF) + t*FF + f];
        }
        // ---- stage Wlin slice (transposed): [j'][a] ----
        for (int ii = tid; ii < HID*NA; ii += NTHREADS) {
            int a = ii >> 6, jp = ii & 63;
            s->wlin[jp*WLS + a] = Wlin[(size_t)a*(TT*HID) + t*HID + jp];
        }
        __syncthreads();

        // ---- gates: acc[pair][gate] = b + x@Wih^T + h@Whh^T (packed f32x2) ----
        u64 acc[4][4];
        #pragma unroll
        for (int p = 0; p < 4; p++)
            #pragma unroll
            for (int g = 0; g < 4; g++)
                acc[p][g] = bias2[g];

        #pragma unroll 8
        for (int f = 0; f < FF; f++) {
            float4 w = s->wih[f*64 + j];
            u64 wd0 = dup2(w.x), wd1 = dup2(w.y), wd2 = dup2(w.z), wd3 = dup2(w.w);
            float4 xa = *reinterpret_cast<const float4*>(&s->xs[f][bbase]);
            float4 xb = *reinterpret_cast<const float4*>(&s->xs[f][bbase+4]);
            u64 xp[4] = { pack2(xa.x, xa.y), pack2(xa.z, xa.w),
                          pack2(xb.x, xb.y), pack2(xb.z, xb.w) };
            #pragma unroll
            for (int p = 0; p < 4; p++) {
                ffma2(acc[p][0], wd0, xp[p]);
                ffma2(acc[p][1], wd1, xp[p]);
                ffma2(acc[p][2], wd2, xp[p]);
                ffma2(acc[p][3], wd3, xp[p]);
            }
        }
        #pragma unroll 8
        for (int k = 0; k < HID; k++) {
            float4 w = s->whh[k*64 + j];
            u64 wd0 = dup2(w.x), wd1 = dup2(w.y), wd2 = dup2(w.z), wd3 = dup2(w.w);
            float4 ha = *reinterpret_cast<const float4*>(&s->h[k][bbase]);
            float4 hb = *reinterpret_cast<const float4*>(&s->h[k][bbase+4]);
            u64 hp[4] = { pack2(ha.x, ha.y), pack2(ha.z, ha.w),
                          pack2(hb.x, hb.y), pack2(hb.z, hb.w) };
            #pragma unroll
            for (int p = 0; p < 4; p++) {
                ffma2(acc[p][0], wd0, hp[p]);
                ffma2(acc[p][1], wd1, hp[p]);
                ffma2(acc[p][2], wd2, hp[p]);
                ffma2(acc[p][3], wd3, hp[p]);
            }
        }

        // ---- pointwise LSTM cell ----
        float hnew[NBQ];
        #pragma unroll
        for (int p = 0; p < 4; p++) {
            float2 gi = unpack2(acc[p][0]);
            float2 gf = unpack2(acc[p][1]);
            float2 gg = unpack2(acc[p][2]);
            float2 go = unpack2(acc[p][3]);
            {
                int b = 2*p;
                float ig = sigm(gi.x), fg = sigm(gf.x);
                float gv = tanh_fast(gg.x), og = sigm(go.x);
                c[b] = fmaf(fg, c[b], ig * gv);
                hnew[b] = og * tanh_fast(c[b]);
            }
            {
                int b = 2*p + 1;
                float ig = sigm(gi.y), fg = sigm(gf.y);
                float gv = tanh_fast(gg.y), og = sigm(go.y);
                c[b] = fmaf(fg, c[b], ig * gv);
                hnew[b] = og * tanh_fast(c[b]);
            }
        }

        __syncthreads();   // all h reads of step t done
        *reinterpret_cast<float4*>(&s->h[j][bbase])   = make_float4(hnew[0], hnew[1], hnew[2], hnew[3]);
        *reinterpret_cast<float4*>(&s->h[j][bbase+4]) = make_float4(hnew[4], hnew[5], hnew[6], hnew[7]);
        __syncthreads();   // new h visible

        // ---- fused readout: logits[a0], logits[a0+1] (packed over batch pairs) ----
        if (has_a) {
            #pragma unroll 8
            for (int jp = 0; jp < HID; jp++) {
                float2 w = *reinterpret_cast<const float2*>(&s->wlin[jp*WLS + a0]);
                u64 w0 = dup2(w.x), w1 = dup2(w.y);
                float4 ha = *reinterpret_cast<const float4*>(&s->h[jp][bbase]);
                float4 hb = *reinterpret_cast<const float4*>(&s->h[jp][bbase+4]);
                u64 hp[4] = { pack2(ha.x, ha.y), pack2(ha.z, ha.w),
                              pack2(hb.x, hb.y), pack2(hb.z, hb.w) };
                #pragma unroll
                for (int p = 0; p < 4; p++) {
                    ffma2(pl0[p], w0, hp[p]);
                    ffma2(pl1[p], w1, hp[p]);
                }
            }
        }
        __syncthreads();   // readout done with wlin/h before next staging
    }

    // ---- logits -> shared (reuse wih area), then softmax + store ----
    float* lg = reinterpret_cast<float*>(&s->wih[0]);   // BB*112 floats = 28 KB < 32 KB
    if (has_a) {
        float ba0 = blin[a0], ba1 = blin[a0 + 1];
        #pragma unroll
        for (int p = 0; p < 4; p++) {
            float2 l0 = unpack2(pl0[p]);
            float2 l1 = unpack2(pl1[p]);
            lg[(bbase + 2*p    )*112 + a0]     = l0.x + ba0;
            lg[(bbase + 2*p    )*112 + a0 + 1] = l1.x + ba1;
            lg[(bbase + 2*p + 1)*112 + a0]     = l0.y + ba0;
            lg[(bbase + 2*p + 1)*112 + a0 + 1] = l1.y + ba1;
        }
    }
    __syncthreads();

    const int warp = tid >> 5, lane = tid & 31;
    #pragma unroll
    for (int r = 0; r < BB/16; r++) {         // 4 rows per warp
        int b = warp*(BB/16) + r;
        float v[4];
        #pragma unroll
        for (int u = 0; u < 4; u++) {
            int a = lane + u*32;
            v[u] = (a < NA) ? lg[b*112 + a] : -INFINITY;
        }
        float m = fmaxf(fmaxf(v[0], v[1]), fmaxf(v[2], v[3]));
        #pragma unroll
        for (int off = 16; off > 0; off >>= 1)
            m = fmaxf(m, __shfl_xor_sync(0xFFFFFFFFu, m, off));
        float e[4]; float ssum = 0.f;
        #pragma unroll
        for (int u = 0; u < 4; u++) {
            int a = lane + u*32;
            e[u] = (a < NA) ? __expf(v[u] - m) : 0.f;
            ssum += e[u];
        }
        #pragma unroll
        for (int off = 16; off > 0; off >>= 1)
            ssum += __shfl_xor_sync(0xFFFFFFFFu, ssum, off);
        float inv = __fdividef(1.f, ssum);
        #pragma unroll
        for (int u = 0; u < 4; u++) {
            int a = lane + u*32;
            if (a < NA)
                out[(size_t)(gb0 + b)*NA + a] = e[u] * inv;
        }
    }
}

extern "C" void kernel_launch(void* const* d_in, const int* in_sizes, int n_in,
                              void* d_out, int out_size) {
    const float* x    = (const float*)d_in[0];
    const float* Wih  = (const float*)d_in[1];
    const float* Whh  = (const float*)d_in[2];
    const float* bih  = (const float*)d_in[3];
    const float* bhh  = (const float*)d_in[4];
    const float* Wlin = (const float*)d_in[5];
    const float* blin = (const float*)d_in[6];
    float* out = (float*)d_out;

    cudaFuncSetAttribute(lstm_fused_kernel,
                         cudaFuncAttributeMaxDynamicSharedMemorySize,
                         (int)sizeof(Smem));
    lstm_fused_kernel<<<8192/BB, NTHREADS, sizeof(Smem)>>>(
        x, Wih, Whh, bih, bhh, Wlin, blin, out);
}

// round 8
// speedup vs baseline: 1.0885x; 1.0885x over previous
#include <cuda_runtime.h>
#include <cuda_bf16.h>
#include <math.h>
#include <cstdint>

#define HID   64
#define TT    128
#define FF    32
#define NA    100
#define NQ    8             // groups of 64 threads
#define NBQ   8             // batch elems per thread
#define BB    (NQ*NBQ)      // 64 batch elems per block
#define NTHREADS (NQ*64)    // 512
#define HS    68            // h/xs row stride in floats
#define WLS   102           // wlin shared stride
#define TF    (TT*FF)
#define TH    (TT*HID)

struct Smem {
    float4 wih[FF*64];        // [f][j] gate-packed (i,f,g,o)   32 KB
    float4 whh[HID*64];       // [k][j] gate-packed             64 KB
    float4 b4g[64];           //                                 1 KB
    float  h[2][HID][HS];     // ping-pong [j'][batch]          34 KB
    float  xs[2][FF][HS];     // double-buffered [f][batch]     17 KB
    float  wlin[2][HID*WLS];  // double-buffered [j'][asset]    51 KB
};

typedef unsigned long long u64;
typedef unsigned int u32;

__device__ __forceinline__ u64 dup2(float v) {
    u64 r; asm("mov.b64 %0, {%1, %1};" : "=l"(r) : "f"(v)); return r;
}
__device__ __forceinline__ u64 pack2(float lo, float hi) {
    u64 r; asm("mov.b64 %0, {%1, %2};" : "=l"(r) : "f"(lo), "f"(hi)); return r;
}
__device__ __forceinline__ void ffma2(u64& d, u64 a, u64 b) {
    asm("fma.rn.f32x2 %0, %1, %2, %0;" : "+l"(d) : "l"(a), "l"(b));
}
__device__ __forceinline__ float2 unpack2(u64 v) {
    float2 r; asm("mov.b64 {%0, %1}, %2;" : "=f"(r.x), "=f"(r.y) : "l"(v)); return r;
}
__device__ __forceinline__ void cpa4(u32 dst, const float* src) {
    asm volatile("cp.async.ca.shared.global [%0], [%1], 4;" :: "r"(dst), "l"(src));
}
__device__ __forceinline__ void cpa_commit() {
    asm volatile("cp.async.commit_group;");
}
__device__ __forceinline__ void cpa_wait_all() {
    asm volatile("cp.async.wait_group 0;");
}

__device__ __forceinline__ float sigm(float v) {
    return __fdividef(1.f, 1.f + __expf(-v));
}
__device__ __forceinline__ float tanh_fast(float v) {
    float a = fabsf(v);
    float e = __expf(-2.f * a);
    float t = __fdividef(1.f - e, 1.f + e);
    return copysignf(t, v);
}

__global__ __launch_bounds__(NTHREADS, 1)
void lstm_fused_kernel(const float* __restrict__ x,
                       const float* __restrict__ Wih,
                       const float* __restrict__ Whh,
                       const float* __restrict__ bih,
                       const float* __restrict__ bhh,
                       const float* __restrict__ Wlin,
                       const float* __restrict__ blin,
                       float* __restrict__ out)
{
    extern __shared__ char smem_raw[];
    Smem* s = reinterpret_cast<Smem*>(smem_raw);

    const int tid   = threadIdx.x;
    const int j     = tid & 63;
    const int q     = tid >> 6;
    const int bbase = q * NBQ;
    const int gb0   = blockIdx.x * BB;

    // ---- async-stage step 0 (x and wlin, buffer 0) ----
    {
        u32 xs0 = (u32)__cvta_generic_to_shared(&s->xs[0][0][0]);
        #pragma unroll
        for (int r = 0; r < (BB*FF)/NTHREADS; r++) {
            int ii = tid + r*NTHREADS;
            int f = ii & 31, b = ii >> 5;
            cpa4(xs0 + (f*HS + b)*4, &x[(size_t)(gb0 + b)*TF + 0*FF + f]);
        }
        u32 wl0 = (u32)__cvta_generic_to_shared(&s->wlin[0][0]);
        #pragma unroll
        for (int r = 0; r < 13; r++) {
            int ii = tid + r*NTHREADS;
            if (ii < HID*NA) {
                int a = ii >> 6, jp = ii & 63;
                cpa4(wl0 + (jp*WLS + a)*4, &Wlin[(size_t)a*TH + 0*HID + jp]);
            }
        }
        cpa_commit();
    }

    // ---- preload weights (gate-packed, transposed) ----
    for (int idx = tid; idx < FF*64; idx += NTHREADS) {
        int f = idx >> 6, jj = idx & 63;
        s->wih[idx] = make_float4(Wih[(0*HID + jj)*FF + f],
                                  Wih[(1*HID + jj)*FF + f],
                                  Wih[(2*HID + jj)*FF + f],
                                  Wih[(3*HID + jj)*FF + f]);
    }
    for (int idx = tid; idx < HID*64; idx += NTHREADS) {
        int k = idx >> 6, jj = idx & 63;
        s->whh[idx] = make_float4(Whh[(0*HID + jj)*HID + k],
                                  Whh[(1*HID + jj)*HID + k],
                                  Whh[(2*HID + jj)*HID + k],
                                  Whh[(3*HID + jj)*HID + k]);
    }
    for (int idx = tid; idx < 64; idx += NTHREADS) {
        s->b4g[idx] = make_float4(bih[0*HID+idx] + bhh[0*HID+idx],
                                  bih[1*HID+idx] + bhh[1*HID+idx],
                                  bih[2*HID+idx] + bhh[2*HID+idx],
                                  bih[3*HID+idx] + bhh[3*HID+idx]);
    }
    {
        float* h0 = &s->h[0][0][0];
        for (int idx = tid; idx < HID*HS; idx += NTHREADS) h0[idx] = 0.f;
    }

    float c[NBQ];
    u64 pl0[4], pl1[4];
    #pragma unroll
    for (int b = 0; b < NBQ; b++) c[b] = 0.f;
    #pragma unroll
    for (int p = 0; p < 4; p++) { pl0[p] = 0ull; pl1[p] = 0ull; }

    const int  a0    = 2 * j;
    const bool has_a = (a0 < NA);

    cpa_wait_all();
    __syncthreads();

    u64 bias2[4];
    {
        float4 bb = s->b4g[j];
        bias2[0] = dup2(bb.x); bias2[1] = dup2(bb.y);
        bias2[2] = dup2(bb.z); bias2[3] = dup2(bb.w);
    }

    int hp = 0;
    for (int t = 0; t < TT; t++) {
        const int cb = t & 1, nb = (t + 1) & 1;

        // ---- async-stage x/wlin for step t+1 (overlaps compute) ----
        if (t + 1 < TT) {
            u32 xsn = (u32)__cvta_generic_to_shared(&s->xs[nb][0][0]);
            #pragma unroll
            for (int r = 0; r < (BB*FF)/NTHREADS; r++) {
                int ii = tid + r*NTHREADS;
                int f = ii & 31, b = ii >> 5;
                cpa4(xsn + (f*HS + b)*4, &x[(size_t)(gb0 + b)*TF + (t+1)*FF + f]);
            }
            u32 wln = (u32)__cvta_generic_to_shared(&s->wlin[nb][0]);
            #pragma unroll
            for (int r = 0; r < 13; r++) {
                int ii = tid + r*NTHREADS;
                if (ii < HID*NA) {
                    int a = ii >> 6, jp = ii & 63;
                    cpa4(wln + (jp*WLS + a)*4, &Wlin[(size_t)a*TH + (t+1)*HID + jp]);
                }
            }
            cpa_commit();
        }

        const float (*hr)[HS] = s->h[hp];
        float (*hw)[HS] = s->h[1 - hp];

        // ---- gates: acc[pair][gate] = b + x@Wih^T + h@Whh^T (packed f32x2) ----
        u64 acc[4][4];
        #pragma unroll
        for (int p = 0; p < 4; p++)
            #pragma unroll
            for (int g = 0; g < 4; g++)
                acc[p][g] = bias2[g];

        #pragma unroll 8
        for (int f = 0; f < FF; f++) {
            float4 w = s->wih[f*64 + j];
            u64 wd0 = dup2(w.x), wd1 = dup2(w.y), wd2 = dup2(w.z), wd3 = dup2(w.w);
            float4 xa = *reinterpret_cast<const float4*>(&s->xs[cb][f][bbase]);
            float4 xb = *reinterpret_cast<const float4*>(&s->xs[cb][f][bbase+4]);
            u64 xp[4] = { pack2(xa.x, xa.y), pack2(xa.z, xa.w),
                          pack2(xb.x, xb.y), pack2(xb.z, xb.w) };
            #pragma unroll
            for (int p = 0; p < 4; p++) {
                ffma2(acc[p][0], wd0, xp[p]);
                ffma2(acc[p][1], wd1, xp[p]);
                ffma2(acc[p][2], wd2, xp[p]);
                ffma2(acc[p][3], wd3, xp[p]);
            }
        }
        #pragma unroll 8
        for (int k = 0; k < HID; k++) {
            float4 w = s->whh[k*64 + j];
            u64 wd0 = dup2(w.x), wd1 = dup2(w.y), wd2 = dup2(w.z), wd3 = dup2(w.w);
            float4 ha = *reinterpret_cast<const float4*>(&hr[k][bbase]);
            float4 hb = *reinterpret_cast<const float4*>(&hr[k][bbase+4]);
            u64 hp4[4] = { pack2(ha.x, ha.y), pack2(ha.z, ha.w),
                           pack2(hb.x, hb.y), pack2(hb.z, hb.w) };
            #pragma unroll
            for (int p = 0; p < 4; p++) {
                ffma2(acc[p][0], wd0, hp4[p]);
                ffma2(acc[p][1], wd1, hp4[p]);
                ffma2(acc[p][2], wd2, hp4[p]);
                ffma2(acc[p][3], wd3, hp4[p]);
            }
        }

        // ---- pointwise LSTM cell ----
        float hnew[NBQ];
        #pragma unroll
        for (int p = 0; p < 4; p++) {
            float2 gi = unpack2(acc[p][0]);
            float2 gf = unpack2(acc[p][1]);
            float2 gg = unpack2(acc[p][2]);
            float2 go = unpack2(acc[p][3]);
            {
                int b = 2*p;
                float ig = sigm(gi.x), fg = sigm(gf.x);
                float gv = tanh_fast(gg.x), og = sigm(go.x);
                c[b] = fmaf(fg, c[b], ig * gv);
                hnew[b] = og * tanh_fast(c[b]);
            }
            {
                int b = 2*p + 1;
                float ig = sigm(gi.y), fg = sigm(gf.y);
                float gv = tanh_fast(gg.y), og = sigm(go.y);
                c[b] = fmaf(fg, c[b], ig * gv);
                hnew[b] = og * tanh_fast(c[b]);
            }
        }

        *reinterpret_cast<float4*>(&hw[j][bbase])   = make_float4(hnew[0], hnew[1], hnew[2], hnew[3]);
        *reinterpret_cast<float4*>(&hw[j][bbase+4]) = make_float4(hnew[4], hnew[5], hnew[6], hnew[7]);
        __syncthreads();   // B1: new h visible for readout

        // ---- fused readout: logits[a0], logits[a0+1] (packed over batch pairs) ----
        if (has_a) {
            #pragma unroll 8
            for (int jp = 0; jp < HID; jp++) {
                float2 w = *reinterpret_cast<const float2*>(&s->wlin[cb][jp*WLS + a0]);
                u64 w0 = dup2(w.x), w1 = dup2(w.y);
                float4 ha = *reinterpret_cast<const float4*>(&hw[jp][bbase]);
                float4 hb = *reinterpret_cast<const float4*>(&hw[jp][bbase+4]);
                u64 hp4[4] = { pack2(ha.x, ha.y), pack2(ha.z, ha.w),
                               pack2(hb.x, hb.y), pack2(hb.z, hb.w) };
                #pragma unroll
                for (int p = 0; p < 4; p++) {
                    ffma2(pl0[p], w0, hp4[p]);
                    ffma2(pl1[p], w1, hp4[p]);
                }
            }
        }

        cpa_wait_all();
        __syncthreads();   // B2: staging landed; readout done (buffers may rotate)
        hp ^= 1;
    }

    // ---- logits -> shared (reuse wih area), then softmax + store ----
    float* lg = reinterpret_cast<float*>(&s->wih[0]);   // BB*112 floats = 28 KB
    if (has_a) {
        float ba0 = blin[a0], ba1 = blin[a0 + 1];
        #pragma unroll
        for (int p = 0; p < 4; p++) {
            float2 l0 = unpack2(pl0[p]);
            float2 l1 = unpack2(pl1[p]);
            lg[(bbase + 2*p    )*112 + a0]     = l0.x + ba0;
            lg[(bbase + 2*p    )*112 + a0 + 1] = l1.x + ba1;
            lg[(bbase + 2*p + 1)*112 + a0]     = l0.y + ba0;
            lg[(bbase + 2*p + 1)*112 + a0 + 1] = l1.y + ba1;
        }
    }
    __syncthreads();

    const int warp = tid >> 5, lane = tid & 31;
    #pragma unroll
    for (int r = 0; r < BB/16; r++) {         // 4 rows per warp
        int b = warp*(BB/16) + r;
        float v[4];
        #pragma unroll
        for (int u = 0; u < 4; u++) {
            int a = lane + u*32;
            v[u] = (a < NA) ? lg[b*112 + a] : -INFINITY;
        }
        float m = fmaxf(fmaxf(v[0], v[1]), fmaxf(v[2], v[3]));
        #pragma unroll
        for (int off = 16; off > 0; off >>= 1)
            m = fmaxf(m, __shfl_xor_sync(0xFFFFFFFFu, m, off));
        float e[4]; float ssum = 0.f;
        #pragma unroll
        for (int u = 0; u < 4; u++) {
            int a = lane + u*32;
            e[u] = (a < NA) ? __expf(v[u] - m) : 0.f;
            ssum += e[u];
        }
        #pragma unroll
        for (int off = 16; off > 0; off >>= 1)
            ssum += __shfl_xor_sync(0xFFFFFFFFu, ssum, off);
        float inv = __fdividef(1.f, ssum);
        #pragma unroll
        for (int u = 0; u < 4; u++) {
            int a = lane + u*32;
            if (a < NA)
                out[(size_t)(gb0 + b)*NA + a] = e[u] * inv;
        }
    }
}

extern "C" void kernel_launch(void* const* d_in, const int* in_sizes, int n_in,
                              void* d_out, int out_size) {
    const float* x    = (const float*)d_in[0];
    const float* Wih  = (const float*)d_in[1];
    const float* Whh  = (const float*)d_in[2];
    const float* bih  = (const float*)d_in[3];
    const float* bhh  = (const float*)d_in[4];
    const float* Wlin = (const float*)d_in[5];
    const float* blin = (const float*)d_in[6];
    float* out = (float*)d_out;

    cudaFuncSetAttribute(lstm_fused_kernel,
                         cudaFuncAttributeMaxDynamicSharedMemorySize,
                         (int)sizeof(Smem));
    lstm_fused_kernel<<<8192/BB, NTHREADS, sizeof(Smem)>>>(
        x, Wih, Whh, bih, bhh, Wlin, blin, out);
}